// round 4
// baseline (speedup 1.0000x reference)
#include <cuda_runtime.h>

// HexEye: mean over 9x9 reflect-padded patches at 721 receptor centers,
// for 32 batches x 3 channels of a 600x800 fp32 image.
//
// d_in[0]: stim        float32 [32, 3, 600, 800]
// d_in[1]: receptor_x  int32   [721]
// d_in[2]: receptor_y  int32   [721]
// d_out  : float32 [32, 3, 721]
//
// One warp per (receptor, group-of-4 bc planes).
// Fast path (patch fully interior): lane -> (row = lane/3, seg = lane%3);
// each lane loads one aligned float4, so ONE LDG.128 with 27 active lanes
// fetches an entire 9x9 patch for a plane. 4 independent plane loads are
// front-batched. Lane-local masked sum + warp reduction.
// Slow path (patch touches border): exact jnp-'reflect' scalar gather.

#define HEX_H     600
#define HEX_W     800
#define HEX_K     9
#define HEX_PAD   4
#define HEX_NOMM  721
#define HEX_BC    96
#define HEX_G     4                         // bc planes per warp
#define HEX_NGRP  (HEX_BC / HEX_G)          // 24
#define HEX_NWARP (HEX_NGRP * HEX_NOMM)     // 17304
#define PLANE     (HEX_H * HEX_W)

__global__ __launch_bounds__(256)
void hexeye_kernel(const float* __restrict__ stim,
                   const int*   __restrict__ receptor_x,
                   const int*   __restrict__ receptor_y,
                   float*       __restrict__ out)
{
    const int gwarp = (blockIdx.x * blockDim.x + threadIdx.x) >> 5;
    const int lane  = threadIdx.x & 31;
    if (gwarp >= HEX_NWARP) return;

    const int o   = gwarp % HEX_NOMM;   // receptor id
    const int grp = gwarp / HEX_NOMM;   // plane group (0..23)

    int cx = __ldg(&receptor_x[o]);
    int cy = __ldg(&receptor_y[o]);
    cx = min(max(cx, HEX_PAD), HEX_W + HEX_PAD - 1);
    cy = min(max(cy, HEX_PAD), HEX_H + HEX_PAD - 1);

    const float* __restrict__ img0 = stim + (size_t)(grp * HEX_G) * PLANE;

    const int m0 = cy - 2 * HEX_PAD;        // top row     of patch
    const int n0 = cx - 2 * HEX_PAD;        // left column of patch
    const int base = n0 & ~3;               // 16B-aligned frame start
    const int w0   = n0 & 3;                // patch offset within frame

    float s[HEX_G];
    #pragma unroll
    for (int g = 0; g < HEX_G; g++) s[g] = 0.0f;

    const bool interior = (m0 >= 0) & (m0 + HEX_K <= HEX_H) &
                          (base >= 0) & (base + 12 <= HEX_W);

    if (interior) {
        // ---- fast vector path ----
        const int row = lane / 3;           // 0..10 (valid < 9)
        const int seg = lane - row * 3;     // 0..2
        const int e0  = 4 * seg;            // element index of v.x in frame

        // per-component validity: element e valid iff w0 <= e < w0+9
        const bool bx = (e0 + 0 >= w0) & (e0 + 0 < w0 + HEX_K);
        const bool by = (e0 + 1 >= w0) & (e0 + 1 < w0 + HEX_K);
        const bool bz = (e0 + 2 >= w0) & (e0 + 2 < w0 + HEX_K);
        const bool bw = (e0 + 3 >= w0) & (e0 + 3 < w0 + HEX_K);

        if (lane < 27) {
            const float* p0 = img0 + (m0 + row) * HEX_W + base + e0;
            float4 v[HEX_G];
            #pragma unroll
            for (int g = 0; g < HEX_G; g++)
                v[g] = __ldg((const float4*)(p0 + g * PLANE));
            #pragma unroll
            for (int g = 0; g < HEX_G; g++) {
                float t = 0.0f;
                if (bx) t += v[g].x;
                if (by) t += v[g].y;
                if (bz) t += v[g].z;
                if (bw) t += v[g].w;
                s[g] = t;
            }
        }
    } else {
        // ---- exact reflect scalar path (border receptors) ----
        #pragma unroll
        for (int i = 0; i < 3; i++) {
            const int idx = lane + 32 * i;          // 0..95, valid < 81
            if (idx < HEX_K * HEX_K) {
                const int dy = idx / HEX_K;
                const int dx = idx - dy * HEX_K;
                int m = m0 + dy;
                int n = n0 + dx;
                m = (m < 0) ? -m : ((m >= HEX_H) ? (2 * HEX_H - 2 - m) : m);
                n = (n < 0) ? -n : ((n >= HEX_W) ? (2 * HEX_W - 2 - n) : n);
                const int off = m * HEX_W + n;
                #pragma unroll
                for (int g = 0; g < HEX_G; g++)
                    s[g] += __ldg(&img0[off + g * PLANE]);
            }
        }
    }

    // warp tree reductions
    #pragma unroll
    for (int off = 16; off > 0; off >>= 1) {
        #pragma unroll
        for (int g = 0; g < HEX_G; g++)
            s[g] += __shfl_xor_sync(0xffffffffu, s[g], off);
    }

    if (lane == 0) {
        const float inv = 1.0f / 81.0f;
        float* op = out + (size_t)(grp * HEX_G) * HEX_NOMM + o;
        #pragma unroll
        for (int g = 0; g < HEX_G; g++)
            op[g * HEX_NOMM] = s[g] * inv;
    }
}

extern "C" void kernel_launch(void* const* d_in, const int* in_sizes, int n_in,
                              void* d_out, int out_size)
{
    const float* stim = (const float*)d_in[0];
    const int*   rx   = (const int*)d_in[1];
    const int*   ry   = (const int*)d_in[2];
    float*       out  = (float*)d_out;

    const int warps_per_block = 256 / 32;  // 8
    const int nblocks = (HEX_NWARP + warps_per_block - 1) / warps_per_block; // 2163

    hexeye_kernel<<<nblocks, 256>>>(stim, rx, ry, out);
}

// round 5
// speedup vs baseline: 1.0239x; 1.0239x over previous
#include <cuda_runtime.h>

// HexEye: mean over 9x9 reflect-padded patches at 721 receptor centers,
// for 32 batches x 3 channels of a 600x800 fp32 image.
//
// d_in[0]: stim        float32 [32, 3, 600, 800]
// d_in[1]: receptor_x  int32   [721]
// d_in[2]: receptor_y  int32   [721]
// d_out  : float32 [32, 3, 721]
//
// One warp per (receptor, group-of-8 bc planes).
// Fast path (patch fully interior): lane -> (row = lane/3, seg = lane%3);
// each lane loads one aligned float4, so ONE LDG.128 with 27 active lanes
// fetches an entire 9x9 patch for a plane. 8 independent plane loads are
// front-batched for MLP. Lane-local masked sum + warp reduction.
// Slow path (patch touches border): exact jnp-'reflect' scalar gather.

#define HEX_H     600
#define HEX_W     800
#define HEX_K     9
#define HEX_PAD   4
#define HEX_NOMM  721
#define HEX_BC    96
#define HEX_G     8                         // bc planes per warp
#define HEX_NGRP  (HEX_BC / HEX_G)          // 12
#define HEX_NWARP (HEX_NGRP * HEX_NOMM)     // 8652
#define PLANE     (HEX_H * HEX_W)

__global__ __launch_bounds__(256)
void hexeye_kernel(const float* __restrict__ stim,
                   const int*   __restrict__ receptor_x,
                   const int*   __restrict__ receptor_y,
                   float*       __restrict__ out)
{
    const int gwarp = (blockIdx.x * blockDim.x + threadIdx.x) >> 5;
    const int lane  = threadIdx.x & 31;
    if (gwarp >= HEX_NWARP) return;

    const int o   = gwarp % HEX_NOMM;   // receptor id
    const int grp = gwarp / HEX_NOMM;   // plane group (0..11)

    int cx = __ldg(&receptor_x[o]);
    int cy = __ldg(&receptor_y[o]);
    cx = min(max(cx, HEX_PAD), HEX_W + HEX_PAD - 1);
    cy = min(max(cy, HEX_PAD), HEX_H + HEX_PAD - 1);

    const float* __restrict__ img0 = stim + (size_t)(grp * HEX_G) * PLANE;

    const int m0 = cy - 2 * HEX_PAD;        // top row     of patch
    const int n0 = cx - 2 * HEX_PAD;        // left column of patch
    const int base = n0 & ~3;               // 16B-aligned frame start
    const int w0   = n0 & 3;                // patch offset within frame

    float s[HEX_G];
    #pragma unroll
    for (int g = 0; g < HEX_G; g++) s[g] = 0.0f;

    const bool interior = (m0 >= 0) & (m0 + HEX_K <= HEX_H) &
                          (base >= 0) & (base + 12 <= HEX_W);

    if (interior) {
        // ---- fast vector path ----
        const int row = lane / 3;           // 0..10 (valid < 9)
        const int seg = lane - row * 3;     // 0..2
        const int e0  = 4 * seg;            // element index of v.x in frame

        // per-component validity: element e valid iff w0 <= e < w0+9
        const bool bx = (e0 + 0 >= w0) & (e0 + 0 < w0 + HEX_K);
        const bool by = (e0 + 1 >= w0) & (e0 + 1 < w0 + HEX_K);
        const bool bz = (e0 + 2 >= w0) & (e0 + 2 < w0 + HEX_K);
        const bool bw = (e0 + 3 >= w0) & (e0 + 3 < w0 + HEX_K);

        if (lane < 27) {
            const float* p0 = img0 + (m0 + row) * HEX_W + base + e0;
            float4 v[HEX_G];
            // front-batch all 8 independent 128-bit loads
            #pragma unroll
            for (int g = 0; g < HEX_G; g++)
                v[g] = __ldg((const float4*)(p0 + g * PLANE));
            #pragma unroll
            for (int g = 0; g < HEX_G; g++) {
                float t = 0.0f;
                if (bx) t += v[g].x;
                if (by) t += v[g].y;
                if (bz) t += v[g].z;
                if (bw) t += v[g].w;
                s[g] = t;
            }
        }
    } else {
        // ---- exact reflect scalar path (border receptors) ----
        #pragma unroll
        for (int i = 0; i < 3; i++) {
            const int idx = lane + 32 * i;          // 0..95, valid < 81
            if (idx < HEX_K * HEX_K) {
                const int dy = idx / HEX_K;
                const int dx = idx - dy * HEX_K;
                int m = m0 + dy;
                int n = n0 + dx;
                m = (m < 0) ? -m : ((m >= HEX_H) ? (2 * HEX_H - 2 - m) : m);
                n = (n < 0) ? -n : ((n >= HEX_W) ? (2 * HEX_W - 2 - n) : n);
                const int off = m * HEX_W + n;
                #pragma unroll
                for (int g = 0; g < HEX_G; g++)
                    s[g] += __ldg(&img0[off + g * PLANE]);
            }
        }
    }

    // warp tree reductions
    #pragma unroll
    for (int off = 16; off > 0; off >>= 1) {
        #pragma unroll
        for (int g = 0; g < HEX_G; g++)
            s[g] += __shfl_xor_sync(0xffffffffu, s[g], off);
    }

    if (lane == 0) {
        const float inv = 1.0f / 81.0f;
        float* op = out + (size_t)(grp * HEX_G) * HEX_NOMM + o;
        #pragma unroll
        for (int g = 0; g < HEX_G; g++)
            op[g * HEX_NOMM] = s[g] * inv;
    }
}

extern "C" void kernel_launch(void* const* d_in, const int* in_sizes, int n_in,
                              void* d_out, int out_size)
{
    const float* stim = (const float*)d_in[0];
    const int*   rx   = (const int*)d_in[1];
    const int*   ry   = (const int*)d_in[2];
    float*       out  = (float*)d_out;

    const int warps_per_block = 256 / 32;  // 8
    const int nblocks = (HEX_NWARP + warps_per_block - 1) / warps_per_block; // 1082

    hexeye_kernel<<<nblocks, 256>>>(stim, rx, ry, out);
}